// round 1
// baseline (speedup 1.0000x reference)
#include <cuda_runtime.h>
#include <math.h>

#define B 64
#define H 128
#define E 128
#define NL 4
#define S 8192
#define V 50257
#define FOURH 512
#define CHUNKS 128   // S / ROWS
#define ROWS 64

#define SZ_LOGITS (B*V)
#define OFF_C  (SZ_LOGITS)
#define OFF_H  (OFF_C + NL*B*H)
#define OFF_ATTN (OFF_H + NL*B*H)

// ---------------- device scratch (no allocations allowed) ----------------
__device__ __align__(16) float g_x[B*H];          // final hidden (x)
__device__ __align__(16) float g_r[B*H];          // Wk @ q  per batch
__device__ float g_cK[B];                          // bk . q
__device__ float g_pm[B*CHUNKS];
__device__ float g_pl[B*CHUNKS];
__device__ __align__(16) float g_pacc[B*CHUNKS*H]; // 4MB partial accumulators
__device__ __align__(16) float g_hln[B*H];

__device__ __forceinline__ float warp_sum(float v) {
#pragma unroll
    for (int o = 16; o > 0; o >>= 1) v += __shfl_xor_sync(0xffffffffu, v, o);
    return v;
}
__device__ __forceinline__ float sigf(float x) { return 1.f / (1.f + __expf(-x)); }

// ============ K1: embed + 4-layer LSTM + q, r = Wk@q, cK = bk.q ============
// 32 blocks x 256 threads, 2 batches per block.
__global__ __launch_bounds__(256) void k_lstm(
    const int* __restrict__ token_id, const float* __restrict__ c0,
    const float* __restrict__ h0, const float* __restrict__ emb,
    const float* __restrict__ Wi, const float* __restrict__ Uh,
    const float* __restrict__ bL, const float* __restrict__ Wq,
    const float* __restrict__ bq, const float* __restrict__ Wk,
    const float* __restrict__ bk, float* __restrict__ out)
{
    __shared__ float xs[2][H];
    __shared__ float hs[2][H];
    __shared__ float gp[2][2][FOURH];   // [k-half][bb][col]
    __shared__ float qs[2][H];

    int tid = threadIdx.x;
    int b0 = blockIdx.x * 2;

    for (int idx = tid; idx < 2*H; idx += 256) {
        int bb = idx >> 7, i = idx & 127;
        xs[bb][i] = emb[(size_t)token_id[b0+bb]*E + i];
    }

    int khalf = tid >> 7;        // 0 or 1: which half of k
    int tc = tid & 127;          // column group: cols [4tc, 4tc+4)
    int cbase = tc * 4;

    for (int l = 0; l < NL; l++) {
        for (int idx = tid; idx < 2*H; idx += 256) {
            int bb = idx >> 7, i = idx & 127;
            hs[bb][i] = h0[((size_t)l*B + b0 + bb)*H + i];
        }
        __syncthreads();

        float4 a0 = {0.f,0.f,0.f,0.f}, a1 = {0.f,0.f,0.f,0.f};
        const float4* Wi4 = (const float4*)(Wi + (size_t)l*E*FOURH);
        const float4* Uh4 = (const float4*)(Uh + (size_t)l*H*FOURH);
        int k0 = khalf * 64;
#pragma unroll 4
        for (int k = k0; k < k0 + 64; k++) {
            float4 w = Wi4[k*(FOURH/4) + tc];
            float4 u = Uh4[k*(FOURH/4) + tc];
            float x0 = xs[0][k], x1 = xs[1][k];
            float hv0 = hs[0][k], hv1 = hs[1][k];
            a0.x += x0*w.x + hv0*u.x; a0.y += x0*w.y + hv0*u.y;
            a0.z += x0*w.z + hv0*u.z; a0.w += x0*w.w + hv0*u.w;
            a1.x += x1*w.x + hv1*u.x; a1.y += x1*w.y + hv1*u.y;
            a1.z += x1*w.z + hv1*u.z; a1.w += x1*w.w + hv1*u.w;
        }
        *(float4*)&gp[khalf][0][cbase] = a0;
        *(float4*)&gp[khalf][1][cbase] = a1;
        __syncthreads();

        // activations: 256 outputs (2 batches x 128)
        {
            int bb = tid >> 7, i = tid & 127;
            const float* bb_l = bL + l*FOURH;
            float ig = gp[0][bb][i]       + gp[1][bb][i]       + bb_l[i];
            float fg = gp[0][bb][128 + i] + gp[1][bb][128 + i] + bb_l[128 + i];
            float gg = gp[0][bb][256 + i] + gp[1][bb][256 + i] + bb_l[256 + i];
            float og = gp[0][bb][384 + i] + gp[1][bb][384 + i] + bb_l[384 + i];
            size_t ofs = ((size_t)l*B + b0 + bb)*H + i;
            float cprev = c0[ofs];
            float cn = sigf(fg)*cprev + sigf(ig)*tanhf(gg);
            float hn = sigf(og)*tanhf(cn);
            out[OFF_C + ofs] = cn;
            out[OFF_H + ofs] = hn;
            xs[bb][i] = hn;   // next-layer input; guarded by sync at loop top
        }
    }
    __syncthreads();

    for (int idx = tid; idx < 2*H; idx += 256) {
        int bb = idx >> 7, i = idx & 127;
        g_x[(b0+bb)*H + i] = xs[bb][i];
    }

    // q[bb][j] = x . Wq[:,j] + bq[j]
    {
        int bb = tid >> 7, j = tid & 127;
        float acc = bq[j];
#pragma unroll 8
        for (int i = 0; i < H; i++) acc += xs[bb][i] * Wq[i*H + j];
        qs[bb][j] = acc;
    }
    __syncthreads();

    // r[bb][i] = Wk[i,:] . q[bb]  (warp per row)
    int wid = tid >> 5, lane = tid & 31;
    for (int row = wid; row < 2*H; row += 8) {
        int bb = row >> 7, i = row & 127;
        float4 wv = ((const float4*)(Wk + (size_t)i*H))[lane];
        float4 qv = ((const float4*)qs[bb])[lane];
        float d = wv.x*qv.x + wv.y*qv.y + wv.z*qv.z + wv.w*qv.w;
        d = warp_sum(d);
        if (lane == 0) g_r[(b0+bb)*H + i] = d;
    }
    if (wid < 2) {
        int bb = wid;
        float p = 0.f;
        for (int j = lane; j < H; j += 32) p += bk[j] * qs[bb][j];
        p = warp_sum(p);
        if (lane == 0) g_cK[b0+bb] = p;
    }
}

// ==== K2: fused attn_mem copy + online-softmax flash pass (split-S) =======
// grid (CHUNKS, B), 256 threads = 8 warps, 8 rows per warp, one float4/lane.
__global__ __launch_bounds__(256) void k_attn_copy(
    const float* __restrict__ attn_mem, const int* __restrict__ step_p,
    float* __restrict__ out)
{
    __shared__ float sm_acc[8][H];
    __shared__ float sm_m[8], sm_l[8];

    int b = blockIdx.y;
    int chunk = blockIdx.x;
    int step = *step_p;
    int tid = threadIdx.x, wid = tid >> 5, lane = tid & 31;

    float4 rf = ((const float4*)(g_r + b*H))[lane];
    float cK = g_cK[b];
    const float sc = 0.08838834764831843f;   // 1/sqrt(128)

    float m = -INFINITY, l = 0.f;
    float4 acc = {0.f,0.f,0.f,0.f};

    int base = chunk*ROWS + wid*8;
    const float4* src = (const float4*)(attn_mem + (size_t)b*S*H);
    float4* dst = (float4*)(out + OFF_ATTN + (size_t)b*S*H);
    const float4* xr = (const float4*)(g_x + b*H);

#pragma unroll
    for (int t = 0; t < 8; t++) {
        int s = base + t;
        float4 v = (s == step) ? xr[lane] : src[(size_t)s*32 + lane];
        dst[(size_t)s*32 + lane] = v;
        if (s <= step) {
            float d = v.x*rf.x + v.y*rf.y + v.z*rf.z + v.w*rf.w;
            d = warp_sum(d);
            float score = (d + cK) * sc;
            float mn = fmaxf(m, score);
            float alpha = __expf(m - mn);   // m=-inf -> 0
            float w = __expf(score - mn);
            l = l*alpha + w;
            acc.x = acc.x*alpha + w*v.x;
            acc.y = acc.y*alpha + w*v.y;
            acc.z = acc.z*alpha + w*v.z;
            acc.w = acc.w*alpha + w*v.w;
            m = mn;
        }
    }
    ((float4*)sm_acc[wid])[lane] = acc;
    if (lane == 0) { sm_m[wid] = m; sm_l[wid] = l; }
    __syncthreads();

    if (tid < H) {
        float M = sm_m[0];
#pragma unroll
        for (int w = 1; w < 8; w++) M = fmaxf(M, sm_m[w]);
        float a = 0.f, L = 0.f;
        if (M > -1e30f) {
#pragma unroll
            for (int w = 0; w < 8; w++) {
                float e = __expf(sm_m[w] - M);
                a += sm_acc[w][tid] * e;
                L += sm_l[w] * e;
            }
        } else {
            M = -INFINITY;
        }
        g_pacc[((size_t)b*CHUNKS + chunk)*H + tid] = a;
        if (tid == 0) { g_pm[b*CHUNKS + chunk] = M; g_pl[b*CHUNKS + chunk] = L; }
    }
}

// ==== K3: combine partials -> ctx -> mix -> tanh -> LayerNorm ============
__global__ __launch_bounds__(128) void k_reduce_mix(
    const float* __restrict__ Wv, const float* __restrict__ bv,
    const float* __restrict__ Wmix, const float* __restrict__ bmix,
    const float* __restrict__ lns, const float* __restrict__ lnb)
{
    __shared__ float es[CHUNKS];
    __shared__ float red[128];
    __shared__ float cp[H], xsm[H], ctxs[H];

    int b = blockIdx.x, t = threadIdx.x;

    float pm = g_pm[b*CHUNKS + t];
    red[t] = pm; __syncthreads();
    for (int o = 64; o > 0; o >>= 1) { if (t < o) red[t] = fmaxf(red[t], red[t+o]); __syncthreads(); }
    float M = red[0]; __syncthreads();

    float e = __expf(pm - M);
    es[t] = e;
    red[t] = g_pl[b*CHUNKS + t] * e; __syncthreads();
    for (int o = 64; o > 0; o >>= 1) { if (t < o) red[t] += red[t+o]; __syncthreads(); }
    float L = red[0]; __syncthreads();

    float a = 0.f;
#pragma unroll 8
    for (int c = 0; c < CHUNKS; c++)
        a += g_pacc[((size_t)b*CHUNKS + c)*H + t] * es[c];
    cp[t] = a / L;
    xsm[t] = g_x[b*H + t];
    __syncthreads();

    float cv = bv[t];
#pragma unroll 8
    for (int i = 0; i < H; i++) cv += cp[i] * Wv[i*H + t];
    ctxs[t] = cv;
    __syncthreads();

    float hm = bmix[t];
#pragma unroll 8
    for (int i = 0; i < H; i++) hm += xsm[i] * Wmix[i*H + t];
#pragma unroll 8
    for (int i = 0; i < H; i++) hm += ctxs[i] * Wmix[(H+i)*H + t];
    hm = tanhf(hm);

    red[t] = hm; __syncthreads();
    for (int o = 64; o > 0; o >>= 1) { if (t < o) red[t] += red[t+o]; __syncthreads(); }
    float mu = red[0] * (1.f/128.f); __syncthreads();
    float d = hm - mu;
    red[t] = d*d; __syncthreads();
    for (int o = 64; o > 0; o >>= 1) { if (t < o) red[t] += red[t+o]; __syncthreads(); }
    float var = red[0] * (1.f/128.f);

    g_hln[b*H + t] = d * rsqrtf(var + 1e-6f) * lns[t] + lnb[t];
}

// ==== K4: logits = h_ln @ Wout + bout, packed f32x2 FMA ===================
__device__ __forceinline__ unsigned long long fma2(
    unsigned long long a, unsigned long long w, unsigned long long c)
{
    unsigned long long d;
    asm("fma.rn.f32x2 %0, %1, %2, %3;" : "=l"(d) : "l"(a), "l"(w), "l"(c));
    return d;
}

__global__ __launch_bounds__(256) void k_logits(
    const float* __restrict__ Wout, const float* __restrict__ bout,
    float* __restrict__ out)
{
    __shared__ unsigned long long hsu[H*(B/2)];  // [k][b-pair], 32KB
    int tid = threadIdx.x;
    float* hsf = (float*)hsu;
    for (int idx = tid; idx < B*H; idx += 256) {
        int b = idx >> 7, k = idx & 127;
        hsf[k*B + b] = g_hln[idx];
    }
    __syncthreads();

    int c = blockIdx.x*256 + tid;
    if (c >= V) return;

    unsigned long long acc[32];
#pragma unroll
    for (int i = 0; i < 32; i++) acc[i] = 0ULL;

#pragma unroll 4
    for (int k = 0; k < H; k++) {
        float w = Wout[(size_t)k*V + c];
        unsigned long long w2;
        asm("mov.b64 %0, {%1, %1};" : "=l"(w2) : "f"(w));
        const ulonglong2* hp = (const ulonglong2*)(hsu + k*(B/2));
#pragma unroll
        for (int p = 0; p < 16; p++) {
            ulonglong2 hv = hp[p];
            acc[2*p]   = fma2(hv.x, w2, acc[2*p]);
            acc[2*p+1] = fma2(hv.y, w2, acc[2*p+1]);
        }
    }
    float bo = bout[c];
#pragma unroll
    for (int p = 0; p < 32; p++) {
        float f0, f1;
        asm("mov.b64 {%0, %1}, %2;" : "=f"(f0), "=f"(f1) : "l"(acc[p]));
        out[(size_t)(2*p)*V + c]     = f0 + bo;
        out[(size_t)(2*p + 1)*V + c] = f1 + bo;
    }
}

// ==========================================================================
extern "C" void kernel_launch(void* const* d_in, const int* in_sizes, int n_in,
                              void* d_out, int out_size)
{
    const int*   token_id = (const int*)  d_in[0];
    const float* c0       = (const float*)d_in[1];
    const float* h0       = (const float*)d_in[2];
    const float* attn_mem = (const float*)d_in[3];
    const int*   step_p   = (const int*)  d_in[4];
    const float* emb      = (const float*)d_in[5];
    const float* Wi       = (const float*)d_in[6];
    const float* Uh       = (const float*)d_in[7];
    const float* bL       = (const float*)d_in[8];
    const float* Wq       = (const float*)d_in[9];
    const float* bq       = (const float*)d_in[10];
    const float* Wk       = (const float*)d_in[11];
    const float* bk       = (const float*)d_in[12];
    const float* Wv       = (const float*)d_in[13];
    const float* bv       = (const float*)d_in[14];
    const float* Wmix     = (const float*)d_in[15];
    const float* bmix     = (const float*)d_in[16];
    const float* lns      = (const float*)d_in[17];
    const float* lnb      = (const float*)d_in[18];
    const float* Wout     = (const float*)d_in[19];
    const float* bout     = (const float*)d_in[20];
    float* out = (float*)d_out;

    k_lstm<<<32, 256>>>(token_id, c0, h0, emb, Wi, Uh, bL, Wq, bq, Wk, bk, out);
    dim3 g2(CHUNKS, B);
    k_attn_copy<<<g2, 256>>>(attn_mem, step_p, out);
    k_reduce_mix<<<B, 128>>>(Wv, bv, Wmix, bmix, lns, lnb);
    k_logits<<<(V + 255)/256, 256>>>(Wout, bout, out);
}

// round 2
// speedup vs baseline: 1.2645x; 1.2645x over previous
#include <cuda_runtime.h>
#include <math.h>

#define B 64
#define H 128
#define E 128
#define NL 4
#define S 8192
#define V 50257
#define FOURH 512
#define CHUNKS 128   // S / ROWS
#define ROWS 64

#define SZ_LOGITS (B*V)
#define OFF_C  (SZ_LOGITS)
#define OFF_H  (OFF_C + NL*B*H)
#define OFF_ATTN (OFF_H + NL*B*H)

typedef unsigned long long ull;

// ---------------- device scratch (no allocations allowed) ----------------
__device__ __align__(16) float g_x[B*H];          // final hidden (x)
__device__ __align__(16) float g_r[B*H];          // Wk @ q  per batch
__device__ float g_cK[B];                          // bk . q
__device__ float g_pm[B*CHUNKS];
__device__ float g_pl[B*CHUNKS];
__device__ __align__(16) float g_pacc[B*CHUNKS*H]; // partial accumulators
__device__ __align__(16) float g_hln[B*H];

__device__ __forceinline__ float warp_sum(float v) {
#pragma unroll
    for (int o = 16; o > 0; o >>= 1) v += __shfl_xor_sync(0xffffffffu, v, o);
    return v;
}
__device__ __forceinline__ float sigf(float x) { return 1.f / (1.f + __expf(-x)); }

__device__ __forceinline__ ull fma2(ull a, ull b, ull c) {
    ull d;
    asm("fma.rn.f32x2 %0, %1, %2, %3;" : "=l"(d) : "l"(a), "l"(b), "l"(c));
    return d;
}
__device__ __forceinline__ ull bcast2(float f) {
    ull d;
    asm("mov.b64 %0, {%1, %1};" : "=l"(d) : "f"(f));
    return d;
}

// ============ K1: embed + 4-layer LSTM + q, r = Wk@q, cK = bk.q ============
// 32 blocks x 256 threads, 2 batches per block, f32x2 FMAs.
__global__ __launch_bounds__(256) void k_lstm(
    const int* __restrict__ token_id, const float* __restrict__ c0,
    const float* __restrict__ h0, const float* __restrict__ emb,
    const float* __restrict__ Wi, const float* __restrict__ Uh,
    const float* __restrict__ bL, const float* __restrict__ Wq,
    const float* __restrict__ bq, const float* __restrict__ Wk,
    const float* __restrict__ bk, float* __restrict__ out)
{
    __shared__ ull xs2[2][H];              // {x,x} broadcast pairs
    __shared__ ull hs2[2][H];              // {h,h} broadcast pairs
    __shared__ float gp[2][2][FOURH];      // [k-half][bb][col]
    __shared__ float qs[2][H];

    int tid = threadIdx.x;
    int b0 = blockIdx.x * 2;

    for (int idx = tid; idx < 2*H; idx += 256) {
        int bb = idx >> 7, i = idx & 127;
        float v = emb[(size_t)token_id[b0+bb]*E + i];
        xs2[bb][i] = bcast2(v);
    }

    int khalf = tid >> 7;        // 0 or 1: which half of k
    int tc = tid & 127;          // column group: cols [4tc, 4tc+4)
    int cbase = tc * 4;

    for (int l = 0; l < NL; l++) {
        for (int idx = tid; idx < 2*H; idx += 256) {
            int bb = idx >> 7, i = idx & 127;
            float v = h0[((size_t)l*B + b0 + bb)*H + i];
            hs2[bb][i] = bcast2(v);
        }
        __syncthreads();

        ull a00 = 0, a01 = 0, a10 = 0, a11 = 0;
        const ulonglong2* Wi2 = (const ulonglong2*)(Wi + (size_t)l*E*FOURH);
        const ulonglong2* Uh2 = (const ulonglong2*)(Uh + (size_t)l*H*FOURH);
        int k0 = khalf * 64;
#pragma unroll 4
        for (int k = k0; k < k0 + 64; k++) {
            ulonglong2 w = Wi2[k*(FOURH/4) + tc];
            ulonglong2 u = Uh2[k*(FOURH/4) + tc];
            ull x0 = xs2[0][k], x1 = xs2[1][k];
            ull hh0 = hs2[0][k], hh1 = hs2[1][k];
            a00 = fma2(w.x, x0, a00);  a01 = fma2(w.y, x0, a01);
            a00 = fma2(u.x, hh0, a00); a01 = fma2(u.y, hh0, a01);
            a10 = fma2(w.x, x1, a10);  a11 = fma2(w.y, x1, a11);
            a10 = fma2(u.x, hh1, a10); a11 = fma2(u.y, hh1, a11);
        }
        *(ull*)&gp[khalf][0][cbase]   = a00;
        *(ull*)&gp[khalf][0][cbase+2] = a01;
        *(ull*)&gp[khalf][1][cbase]   = a10;
        *(ull*)&gp[khalf][1][cbase+2] = a11;
        __syncthreads();

        // activations: 256 outputs (2 batches x 128)
        {
            int bb = tid >> 7, i = tid & 127;
            const float* bb_l = bL + l*FOURH;
            float ig = gp[0][bb][i]       + gp[1][bb][i]       + bb_l[i];
            float fg = gp[0][bb][128 + i] + gp[1][bb][128 + i] + bb_l[128 + i];
            float gg = gp[0][bb][256 + i] + gp[1][bb][256 + i] + bb_l[256 + i];
            float og = gp[0][bb][384 + i] + gp[1][bb][384 + i] + bb_l[384 + i];
            size_t ofs = ((size_t)l*B + b0 + bb)*H + i;
            float cprev = c0[ofs];
            float cn = sigf(fg)*cprev + sigf(ig)*tanhf(gg);
            float hn = sigf(og)*tanhf(cn);
            out[OFF_C + ofs] = cn;
            out[OFF_H + ofs] = hn;
            xs2[bb][i] = bcast2(hn);   // next-layer input; guarded by sync at loop top
        }
    }
    __syncthreads();

    for (int idx = tid; idx < 2*H; idx += 256) {
        int bb = idx >> 7, i = idx & 127;
        g_x[(b0+bb)*H + i] = ((const float2*)&xs2[bb][i])->x;
    }

    // q[bb][j] = x . Wq[:,j] + bq[j]
    {
        int bb = tid >> 7, j = tid & 127;
        float acc = bq[j];
#pragma unroll 8
        for (int i = 0; i < H; i++)
            acc += ((const float2*)&xs2[bb][i])->x * Wq[i*H + j];
        qs[bb][j] = acc;
    }
    __syncthreads();

    // r[bb][i] = Wk[i,:] . q[bb]  (warp per row)
    int wid = tid >> 5, lane = tid & 31;
    for (int row = wid; row < 2*H; row += 8) {
        int bb = row >> 7, i = row & 127;
        float4 wv = ((const float4*)(Wk + (size_t)i*H))[lane];
        float4 qv = ((const float4*)qs[bb])[lane];
        float d = wv.x*qv.x + wv.y*qv.y + wv.z*qv.z + wv.w*qv.w;
        d = warp_sum(d);
        if (lane == 0) g_r[(b0+bb)*H + i] = d;
    }
    if (wid < 2) {
        int bb = wid;
        float p = 0.f;
        for (int j = lane; j < H; j += 32) p += bk[j] * qs[bb][j];
        p = warp_sum(p);
        if (lane == 0) g_cK[b0+bb] = p;
    }
}

// ==== K2: fused attn_mem copy + flash pass (split-S, latency-overlapped) ===
// grid (CHUNKS, B), 256 threads = 8 warps, 8 rows per warp, one float4/lane.
__global__ __launch_bounds__(256) void k_attn_copy(
    const float* __restrict__ attn_mem, const int* __restrict__ step_p,
    float* __restrict__ out)
{
    __shared__ float sm_acc[8][H];
    __shared__ float sm_m[8], sm_l[8];

    int b = blockIdx.y;
    int chunk = blockIdx.x;
    int step = *step_p;
    int tid = threadIdx.x, wid = tid >> 5, lane = tid & 31;
    int base = chunk*ROWS + wid*8;

    const float4* src = (const float4*)(attn_mem + (size_t)b*S*H);
    float4* dst = (float4*)(out + OFF_ATTN + (size_t)b*S*H);

    if (chunk*ROWS > step) {
        // pure copy: 8 independent loads, 8 independent stores; no bookkeeping
        float4 v[8];
#pragma unroll
        for (int t = 0; t < 8; t++) v[t] = src[(size_t)(base+t)*32 + lane];
#pragma unroll
        for (int t = 0; t < 8; t++) dst[(size_t)(base+t)*32 + lane] = v[t];
        return;
    }

    const float4* xr = (const float4*)(g_x + b*H);
    float4 rf = ((const float4*)(g_r + b*H))[lane];
    float cK = g_cK[b];
    const float scl = 0.08838834764831843f;   // 1/sqrt(128)

    float4 v[8];
#pragma unroll
    for (int t = 0; t < 8; t++) {
        int s = base + t;
        v[t] = (s == step) ? xr[lane] : src[(size_t)s*32 + lane];
    }
#pragma unroll
    for (int t = 0; t < 8; t++) dst[(size_t)(base+t)*32 + lane] = v[t];

    // 8 independent partial dots, then 8 interleaved butterfly reductions
    float d[8];
#pragma unroll
    for (int t = 0; t < 8; t++)
        d[t] = v[t].x*rf.x + v[t].y*rf.y + v[t].z*rf.z + v[t].w*rf.w;
#pragma unroll
    for (int o = 16; o > 0; o >>= 1) {
#pragma unroll
        for (int t = 0; t < 8; t++)
            d[t] += __shfl_xor_sync(0xffffffffu, d[t], o);
    }

    // max-first softmax over the warp's 8 rows (no serial rescale chain)
    float sct[8];
    float m = -INFINITY;
#pragma unroll
    for (int t = 0; t < 8; t++) {
        sct[t] = (base + t <= step) ? (d[t] + cK) * scl : -INFINITY;
        m = fmaxf(m, sct[t]);
    }
    float l = 0.f;
    float4 acc = {0.f, 0.f, 0.f, 0.f};
#pragma unroll
    for (int t = 0; t < 8; t++) {
        float w = (base + t <= step) ? __expf(sct[t] - m) : 0.f;
        l += w;
        acc.x += w*v[t].x; acc.y += w*v[t].y;
        acc.z += w*v[t].z; acc.w += w*v[t].w;
    }
    ((float4*)sm_acc[wid])[lane] = acc;
    if (lane == 0) { sm_m[wid] = m; sm_l[wid] = l; }
    __syncthreads();

    if (tid < H) {
        float M = sm_m[0];
#pragma unroll
        for (int w = 1; w < 8; w++) M = fmaxf(M, sm_m[w]);
        float a = 0.f, L = 0.f;
#pragma unroll
        for (int w = 0; w < 8; w++) {
            float e = __expf(sm_m[w] - M);   // exp(-inf - finite) = 0
            a += sm_acc[w][tid] * e;
            L += sm_l[w] * e;
        }
        g_pacc[((size_t)b*CHUNKS + chunk)*H + tid] = a;
        if (tid == 0) { g_pm[b*CHUNKS + chunk] = M; g_pl[b*CHUNKS + chunk] = L; }
    }
}

// ==== K3: combine partials -> ctx -> mix -> tanh -> LayerNorm ============
__global__ __launch_bounds__(128) void k_reduce_mix(
    const int* __restrict__ step_p,
    const float* __restrict__ Wv, const float* __restrict__ bv,
    const float* __restrict__ Wmix, const float* __restrict__ bmix,
    const float* __restrict__ lns, const float* __restrict__ lnb)
{
    __shared__ float es[CHUNKS];
    __shared__ float red[128];
    __shared__ float cp[H], xsm[H], ctxs[H];

    int b = blockIdx.x, t = threadIdx.x;
    int nact = (*step_p >> 6) + 1;   // chunks [0, nact) touched attention

    float pm = (t < nact) ? g_pm[b*CHUNKS + t] : -INFINITY;
    float pl = (t < nact) ? g_pl[b*CHUNKS + t] : 0.f;

    red[t] = pm; __syncthreads();
    for (int o = 64; o > 0; o >>= 1) { if (t < o) red[t] = fmaxf(red[t], red[t+o]); __syncthreads(); }
    float M = red[0]; __syncthreads();

    float e = __expf(pm - M);        // pm=-inf -> 0 (M finite: chunk 0 active)
    es[t] = e;
    red[t] = pl * e; __syncthreads();
    for (int o = 64; o > 0; o >>= 1) { if (t < o) red[t] += red[t+o]; __syncthreads(); }
    float L = red[0]; __syncthreads();

    float a = 0.f;
#pragma unroll 4
    for (int c = 0; c < nact; c++)
        a += g_pacc[((size_t)b*CHUNKS + c)*H + t] * es[c];
    cp[t] = a / L;
    xsm[t] = g_x[b*H + t];
    __syncthreads();

    float cv = bv[t];
#pragma unroll 8
    for (int i = 0; i < H; i++) cv += cp[i] * Wv[i*H + t];
    ctxs[t] = cv;
    __syncthreads();

    float hm = bmix[t];
#pragma unroll 8
    for (int i = 0; i < H; i++) hm += xsm[i] * Wmix[i*H + t];
#pragma unroll 8
    for (int i = 0; i < H; i++) hm += ctxs[i] * Wmix[(H+i)*H + t];
    hm = tanhf(hm);

    red[t] = hm; __syncthreads();
    for (int o = 64; o > 0; o >>= 1) { if (t < o) red[t] += red[t+o]; __syncthreads(); }
    float mu = red[0] * (1.f/128.f); __syncthreads();
    float d = hm - mu;
    red[t] = d*d; __syncthreads();
    for (int o = 64; o > 0; o >>= 1) { if (t < o) red[t] += red[t+o]; __syncthreads(); }
    float var = red[0] * (1.f/128.f);

    g_hln[b*H + t] = d * rsqrtf(var + 1e-6f) * lns[t] + lnb[t];
}

// ==== K4: logits = h_ln @ Wout + bout; 2 cols x 32 batches / thread ======
// grid (ceil(V/512), 2).  f32x2 FMAs, h staged k-major in smem.
__global__ __launch_bounds__(256, 2) void k_logits(
    const float* __restrict__ Wout, const float* __restrict__ bout,
    float* __restrict__ out)
{
    __shared__ ull hsu[H*16];   // [k][batch-pair] for this 32-batch half: 16KB
    int tid = threadIdx.x;
    int bh = blockIdx.y;        // batch half: batches [bh*32, bh*32+32)
    float* hsf = (float*)hsu;
    for (int idx = tid; idx < 32*H; idx += 256) {
        int k = idx >> 5, bb = idx & 31;
        hsf[k*32 + bb] = g_hln[(bh*32 + bb)*H + k];
    }
    __syncthreads();

    int c0 = (blockIdx.x*256 + tid) * 2;
    if (c0 >= V) return;
    size_t off2 = (c0 + 1 < V) ? 1 : 0;   // duplicate load for the odd tail col

    ull acc0[16], acc1[16];
#pragma unroll
    for (int i = 0; i < 16; i++) { acc0[i] = 0ULL; acc1[i] = 0ULL; }

#pragma unroll 4
    for (int k = 0; k < H; k++) {
        float wa = Wout[(size_t)k*V + c0];
        float wb = Wout[(size_t)k*V + c0 + off2];
        ull w2a = bcast2(wa);
        ull w2b = bcast2(wb);
        const ulonglong2* hp = (const ulonglong2*)(hsu + k*16);
#pragma unroll
        for (int p = 0; p < 8; p++) {
            ulonglong2 hv = hp[p];
            acc0[2*p]   = fma2(hv.x, w2a, acc0[2*p]);
            acc0[2*p+1] = fma2(hv.y, w2a, acc0[2*p+1]);
            acc1[2*p]   = fma2(hv.x, w2b, acc1[2*p]);
            acc1[2*p+1] = fma2(hv.y, w2b, acc1[2*p+1]);
        }
    }

    float bo0 = bout[c0];
    float bo1 = bout[c0 + off2];
#pragma unroll
    for (int p = 0; p < 16; p++) {
        float f0, f1;
        asm("mov.b64 {%0, %1}, %2;" : "=f"(f0), "=f"(f1) : "l"(acc0[p]));
        int b0r = bh*32 + 2*p;
        out[(size_t)b0r*V + c0]     = f0 + bo0;
        out[(size_t)(b0r+1)*V + c0] = f1 + bo0;
    }
    if (off2) {
#pragma unroll
        for (int p = 0; p < 16; p++) {
            float f0, f1;
            asm("mov.b64 {%0, %1}, %2;" : "=f"(f0), "=f"(f1) : "l"(acc1[p]));
            int b0r = bh*32 + 2*p;
            out[(size_t)b0r*V + c0 + 1]     = f0 + bo1;
            out[(size_t)(b0r+1)*V + c0 + 1] = f1 + bo1;
        }
    }
}

// ==========================================================================
extern "C" void kernel_launch(void* const* d_in, const int* in_sizes, int n_in,
                              void* d_out, int out_size)
{
    const int*   token_id = (const int*)  d_in[0];
    const float* c0       = (const float*)d_in[1];
    const float* h0       = (const float*)d_in[2];
    const float* attn_mem = (const float*)d_in[3];
    const int*   step_p   = (const int*)  d_in[4];
    const float* emb      = (const float*)d_in[5];
    const float* Wi       = (const float*)d_in[6];
    const float* Uh       = (const float*)d_in[7];
    const float* bL       = (const float*)d_in[8];
    const float* Wq       = (const float*)d_in[9];
    const float* bq       = (const float*)d_in[10];
    const float* Wk       = (const float*)d_in[11];
    const float* bk       = (const float*)d_in[12];
    const float* Wv       = (const float*)d_in[13];
    const float* bv       = (const float*)d_in[14];
    const float* Wmix     = (const float*)d_in[15];
    const float* bmix     = (const float*)d_in[16];
    const float* lns      = (const float*)d_in[17];
    const float* lnb      = (const float*)d_in[18];
    const float* Wout     = (const float*)d_in[19];
    const float* bout     = (const float*)d_in[20];
    float* out = (float*)d_out;

    k_lstm<<<32, 256>>>(token_id, c0, h0, emb, Wi, Uh, bL, Wq, bq, Wk, bk, out);
    dim3 g2(CHUNKS, B);
    k_attn_copy<<<g2, 256>>>(attn_mem, step_p, out);
    k_reduce_mix<<<B, 128>>>(step_p, Wv, bv, Wmix, bmix, lns, lnb);
    dim3 g4((V + 511)/512, 2);
    k_logits<<<g4, 256>>>(Wout, bout, out);
}

// round 3
// speedup vs baseline: 1.6122x; 1.2749x over previous
#include <cuda_runtime.h>
#include <math.h>

#define B 64
#define H 128
#define E 128
#define NL 4
#define S 8192
#define V 50257
#define FOURH 512
#define CHUNKS 128   // S / ROWS
#define ROWS 64

#define SZ_LOGITS (B*V)
#define OFF_C  (SZ_LOGITS)
#define OFF_H  (OFF_C + NL*B*H)
#define OFF_ATTN (OFF_H + NL*B*H)

typedef unsigned long long ull;

// ---------------- device scratch (no allocations allowed) ----------------
__device__ __align__(16) float g_x[B*H];          // final hidden (x)
__device__ __align__(16) float g_r[B*H];          // Wk @ q  per batch
__device__ float g_cK[B];                          // bk . q
__device__ float g_pm[B*CHUNKS];
__device__ float g_pl[B*CHUNKS];
__device__ __align__(16) float g_pacc[B*CHUNKS*H]; // partial accumulators
__device__ __align__(16) float g_hln[B*H];

__device__ __forceinline__ float warp_sum(float v) {
#pragma unroll
    for (int o = 16; o > 0; o >>= 1) v += __shfl_xor_sync(0xffffffffu, v, o);
    return v;
}
__device__ __forceinline__ float sigf(float x) { return 1.f / (1.f + __expf(-x)); }

__device__ __forceinline__ ull fma2(ull a, ull b, ull c) {
    ull d;
    asm("fma.rn.f32x2 %0, %1, %2, %3;" : "=l"(d) : "l"(a), "l"(b), "l"(c));
    return d;
}
__device__ __forceinline__ ull bcast2(float f) {
    ull d;
    asm("mov.b64 %0, {%1, %1};" : "=l"(d) : "f"(f));
    return d;
}

// ============ K1: embed + 4-layer LSTM + q, r = Wk@q, cK = bk.q ============
// 32 blocks x 256 threads, 2 batches per block, f32x2 FMAs.
__global__ __launch_bounds__(256) void k_lstm(
    const int* __restrict__ token_id, const float* __restrict__ c0,
    const float* __restrict__ h0, const float* __restrict__ emb,
    const float* __restrict__ Wi, const float* __restrict__ Uh,
    const float* __restrict__ bL, const float* __restrict__ Wq,
    const float* __restrict__ bq, const float* __restrict__ Wk,
    const float* __restrict__ bk, float* __restrict__ out)
{
    __shared__ ull xs2[2][H];              // {x,x} broadcast pairs
    __shared__ ull hs2[2][H];              // {h,h} broadcast pairs
    __shared__ float gp[2][2][FOURH];      // [k-half][bb][col]
    __shared__ float qs[2][H];

    int tid = threadIdx.x;
    int b0 = blockIdx.x * 2;

    for (int idx = tid; idx < 2*H; idx += 256) {
        int bb = idx >> 7, i = idx & 127;
        float v = emb[(size_t)token_id[b0+bb]*E + i];
        xs2[bb][i] = bcast2(v);
    }

    int khalf = tid >> 7;        // 0 or 1: which half of k
    int tc = tid & 127;          // column group: cols [4tc, 4tc+4)
    int cbase = tc * 4;

    for (int l = 0; l < NL; l++) {
        for (int idx = tid; idx < 2*H; idx += 256) {
            int bb = idx >> 7, i = idx & 127;
            float v = h0[((size_t)l*B + b0 + bb)*H + i];
            hs2[bb][i] = bcast2(v);
        }
        __syncthreads();

        ull a00 = 0, a01 = 0, a10 = 0, a11 = 0;
        const ulonglong2* Wi2 = (const ulonglong2*)(Wi + (size_t)l*E*FOURH);
        const ulonglong2* Uh2 = (const ulonglong2*)(Uh + (size_t)l*H*FOURH);
        int k0 = khalf * 64;
#pragma unroll 4
        for (int k = k0; k < k0 + 64; k++) {
            ulonglong2 w = Wi2[k*(FOURH/4) + tc];
            ulonglong2 u = Uh2[k*(FOURH/4) + tc];
            ull x0 = xs2[0][k], x1 = xs2[1][k];
            ull hh0 = hs2[0][k], hh1 = hs2[1][k];
            a00 = fma2(w.x, x0, a00);  a01 = fma2(w.y, x0, a01);
            a00 = fma2(u.x, hh0, a00); a01 = fma2(u.y, hh0, a01);
            a10 = fma2(w.x, x1, a10);  a11 = fma2(w.y, x1, a11);
            a10 = fma2(u.x, hh1, a10); a11 = fma2(u.y, hh1, a11);
        }
        *(ull*)&gp[khalf][0][cbase]   = a00;
        *(ull*)&gp[khalf][0][cbase+2] = a01;
        *(ull*)&gp[khalf][1][cbase]   = a10;
        *(ull*)&gp[khalf][1][cbase+2] = a11;
        __syncthreads();

        // activations: 256 outputs (2 batches x 128)
        {
            int bb = tid >> 7, i = tid & 127;
            const float* bb_l = bL + l*FOURH;
            float ig = gp[0][bb][i]       + gp[1][bb][i]       + bb_l[i];
            float fg = gp[0][bb][128 + i] + gp[1][bb][128 + i] + bb_l[128 + i];
            float gg = gp[0][bb][256 + i] + gp[1][bb][256 + i] + bb_l[256 + i];
            float og = gp[0][bb][384 + i] + gp[1][bb][384 + i] + bb_l[384 + i];
            size_t ofs = ((size_t)l*B + b0 + bb)*H + i;
            float cprev = c0[ofs];
            float cn = sigf(fg)*cprev + sigf(ig)*tanhf(gg);
            float hn = sigf(og)*tanhf(cn);
            out[OFF_C + ofs] = cn;
            out[OFF_H + ofs] = hn;
            xs2[bb][i] = bcast2(hn);   // next-layer input; guarded by sync at loop top
        }
    }
    __syncthreads();

    for (int idx = tid; idx < 2*H; idx += 256) {
        int bb = idx >> 7, i = idx & 127;
        g_x[(b0+bb)*H + i] = ((const float2*)&xs2[bb][i])->x;
    }

    // q[bb][j] = x . Wq[:,j] + bq[j]
    {
        int bb = tid >> 7, j = tid & 127;
        float acc = bq[j];
#pragma unroll 8
        for (int i = 0; i < H; i++)
            acc += ((const float2*)&xs2[bb][i])->x * Wq[i*H + j];
        qs[bb][j] = acc;
    }
    __syncthreads();

    // r[bb][i] = Wk[i,:] . q[bb]  (warp per row)
    int wid = tid >> 5, lane = tid & 31;
    for (int row = wid; row < 2*H; row += 8) {
        int bb = row >> 7, i = row & 127;
        float4 wv = ((const float4*)(Wk + (size_t)i*H))[lane];
        float4 qv = ((const float4*)qs[bb])[lane];
        float d = wv.x*qv.x + wv.y*qv.y + wv.z*qv.z + wv.w*qv.w;
        d = warp_sum(d);
        if (lane == 0) g_r[(b0+bb)*H + i] = d;
    }
    if (wid < 2) {
        int bb = wid;
        float p = 0.f;
        for (int j = lane; j < H; j += 32) p += bk[j] * qs[bb][j];
        p = warp_sum(p);
        if (lane == 0) g_cK[b0+bb] = p;
    }
}

// ==== K2: fused attn_mem copy + flash pass (split-S, latency-overlapped) ===
// grid (CHUNKS, B), 256 threads = 8 warps, 8 rows per warp, one float4/lane.
__global__ __launch_bounds__(256) void k_attn_copy(
    const float* __restrict__ attn_mem, const int* __restrict__ step_p,
    float* __restrict__ out)
{
    __shared__ float sm_acc[8][H];
    __shared__ float sm_m[8], sm_l[8];

    int b = blockIdx.y;
    int chunk = blockIdx.x;
    int step = *step_p;
    int tid = threadIdx.x, wid = tid >> 5, lane = tid & 31;
    int base = chunk*ROWS + wid*8;

    const float4* src = (const float4*)(attn_mem + (size_t)b*S*H);
    float4* dst = (float4*)(out + OFF_ATTN + (size_t)b*S*H);

    if (chunk*ROWS > step) {
        // pure copy: streaming loads/stores, no L2 retention
        float4 v[8];
#pragma unroll
        for (int t = 0; t < 8; t++) v[t] = __ldcs(&src[(size_t)(base+t)*32 + lane]);
#pragma unroll
        for (int t = 0; t < 8; t++) __stcs(&dst[(size_t)(base+t)*32 + lane], v[t]);
        return;
    }

    const float4* xr = (const float4*)(g_x + b*H);
    float4 rf = ((const float4*)(g_r + b*H))[lane];
    float cK = g_cK[b];
    const float scl = 0.08838834764831843f;   // 1/sqrt(128)

    float4 v[8];
#pragma unroll
    for (int t = 0; t < 8; t++) {
        int s = base + t;
        v[t] = (s == step) ? xr[lane] : __ldcs(&src[(size_t)s*32 + lane]);
    }
#pragma unroll
    for (int t = 0; t < 8; t++) __stcs(&dst[(size_t)(base+t)*32 + lane], v[t]);

    // 8 independent partial dots, then 8 interleaved butterfly reductions
    float d[8];
#pragma unroll
    for (int t = 0; t < 8; t++)
        d[t] = v[t].x*rf.x + v[t].y*rf.y + v[t].z*rf.z + v[t].w*rf.w;
#pragma unroll
    for (int o = 16; o > 0; o >>= 1) {
#pragma unroll
        for (int t = 0; t < 8; t++)
            d[t] += __shfl_xor_sync(0xffffffffu, d[t], o);
    }

    // max-first softmax over the warp's 8 rows (no serial rescale chain)
    float sct[8];
    float m = -INFINITY;
#pragma unroll
    for (int t = 0; t < 8; t++) {
        sct[t] = (base + t <= step) ? (d[t] + cK) * scl : -INFINITY;
        m = fmaxf(m, sct[t]);
    }
    float l = 0.f;
    float4 acc = {0.f, 0.f, 0.f, 0.f};
#pragma unroll
    for (int t = 0; t < 8; t++) {
        float w = (base + t <= step) ? __expf(sct[t] - m) : 0.f;
        l += w;
        acc.x += w*v[t].x; acc.y += w*v[t].y;
        acc.z += w*v[t].z; acc.w += w*v[t].w;
    }
    ((float4*)sm_acc[wid])[lane] = acc;
    if (lane == 0) { sm_m[wid] = m; sm_l[wid] = l; }
    __syncthreads();

    if (tid < H) {
        float M = sm_m[0];
#pragma unroll
        for (int w = 1; w < 8; w++) M = fmaxf(M, sm_m[w]);
        float a = 0.f, L = 0.f;
#pragma unroll
        for (int w = 0; w < 8; w++) {
            float e = __expf(sm_m[w] - M);   // exp(-inf - finite) = 0
            a += sm_acc[w][tid] * e;
            L += sm_l[w] * e;
        }
        g_pacc[((size_t)b*CHUNKS + chunk)*H + tid] = a;
        if (tid == 0) { g_pm[b*CHUNKS + chunk] = M; g_pl[b*CHUNKS + chunk] = L; }
    }
}

// ==== K3: combine partials -> ctx -> mix -> tanh -> LayerNorm ============
// 256 threads: dot-product i-ranges split across two 128-thread halves.
__global__ __launch_bounds__(256) void k_reduce_mix(
    const int* __restrict__ step_p,
    const float* __restrict__ Wv, const float* __restrict__ bv,
    const float* __restrict__ Wmix, const float* __restrict__ bmix,
    const float* __restrict__ lns, const float* __restrict__ lnb)
{
    __shared__ float es[CHUNKS];
    __shared__ float red[128];
    __shared__ float part[256];
    __shared__ float cp[H], xsm[H], ctxs[H];

    int b = blockIdx.x;
    int tid = threadIdx.x;
    int t = tid & 127, half = tid >> 7;
    int nact = (*step_p >> 6) + 1;   // chunks [0, nact) touched attention

    if (tid < 128) {
        float pm = (tid < nact) ? g_pm[b*CHUNKS + tid] : -INFINITY;
        red[tid] = pm;
    }
    __syncthreads();
    for (int o = 64; o > 0; o >>= 1) {
        if (tid < o) red[tid] = fmaxf(red[tid], red[tid+o]);
        __syncthreads();
    }
    float M = red[0];
    __syncthreads();

    if (tid < 128) {
        float pm = (tid < nact) ? g_pm[b*CHUNKS + tid] : -INFINITY;
        float pl = (tid < nact) ? g_pl[b*CHUNKS + tid] : 0.f;
        float e = __expf(pm - M);    // pm=-inf -> 0
        es[tid] = e;
        red[tid] = pl * e;
    }
    __syncthreads();
    for (int o = 64; o > 0; o >>= 1) {
        if (tid < o) red[tid] += red[tid+o];
        __syncthreads();
    }
    float L = red[0];
    __syncthreads();

    // combine partial accumulators: chunk range split by half
    {
        float a = 0.f;
#pragma unroll 4
        for (int c = half; c < nact; c += 2)
            a += g_pacc[((size_t)b*CHUNKS + c)*H + t] * es[c];
        part[tid] = a;
    }
    __syncthreads();
    if (tid < 128) {
        cp[t] = (part[t] + part[t+128]) / L;
        xsm[t] = g_x[b*H + t];
    }
    __syncthreads();

    // ctx = cp @ Wv + bv, split i
    {
        float cv = 0.f;
        int i0 = half*64;
#pragma unroll 8
        for (int i = i0; i < i0 + 64; i++) cv += cp[i] * Wv[i*H + t];
        part[tid] = cv;
    }
    __syncthreads();
    if (tid < 128) ctxs[t] = part[t] + part[t+128] + bv[t];
    __syncthreads();

    // h_mix = tanh([x; ctx] @ Wmix + bmix), split i over 256
    {
        float hm = 0.f;
        if (half == 0) {
#pragma unroll 8
            for (int i = 0; i < 128; i++) hm += xsm[i] * Wmix[i*H + t];
        } else {
#pragma unroll 8
            for (int i = 0; i < 128; i++) hm += ctxs[i] * Wmix[(H+i)*H + t];
        }
        part[tid] = hm;
    }
    __syncthreads();

    float hv = 0.f;
    if (tid < 128) {
        hv = tanhf(part[t] + part[t+128] + bmix[t]);
        red[t] = hv;
    }
    __syncthreads();
    for (int o = 64; o > 0; o >>= 1) {
        if (tid < o) red[tid] += red[tid+o];
        __syncthreads();
    }
    float mu = red[0] * (1.f/128.f);
    __syncthreads();
    float dv = hv - mu;
    if (tid < 128) red[t] = dv*dv;
    __syncthreads();
    for (int o = 64; o > 0; o >>= 1) {
        if (tid < o) red[tid] += red[tid+o];
        __syncthreads();
    }
    float var = red[0] * (1.f/128.f);

    if (tid < 128)
        g_hln[b*H + t] = dv * rsqrtf(var + 1e-6f) * lns[t] + lnb[t];
}

// ==== K4: logits = h_ln @ Wout + bout; 2 cols (c, c+256) x 16 batches =====
// grid (ceil(V/512), 4), 3 blocks/SM target.
__global__ __launch_bounds__(256, 3) void k_logits(
    const float* __restrict__ Wout, const float* __restrict__ bout,
    float* __restrict__ out)
{
    __shared__ ull hsu[H*8];   // [k][batch-pair] for this 16-batch quarter: 8KB
    int tid = threadIdx.x;
    int bq = blockIdx.y;       // batches [bq*16, bq*16+16)
    float* hsf = (float*)hsu;
    for (int idx = tid; idx < 16*H; idx += 256) {
        int k = idx >> 4, bb = idx & 15;
        hsf[k*16 + bb] = g_hln[(bq*16 + bb)*H + k];
    }
    __syncthreads();

    int base = blockIdx.x * 512;
    int ca = base + tid;            // column A
    int cb = ca + 256;              // column B
    int ca_ok = (ca < V), cb_ok = (cb < V);
    int ca_c = ca_ok ? ca : (V-1);
    int cb_c = cb_ok ? cb : (V-1);

    ull acc0[8], acc1[8];
#pragma unroll
    for (int i = 0; i < 8; i++) { acc0[i] = 0ULL; acc1[i] = 0ULL; }

#pragma unroll 4
    for (int k = 0; k < H; k++) {
        float wa = Wout[(size_t)k*V + ca_c];
        float wb = Wout[(size_t)k*V + cb_c];
        ull w2a = bcast2(wa);
        ull w2b = bcast2(wb);
        const ulonglong2* hp = (const ulonglong2*)(hsu + k*8);
#pragma unroll
        for (int p = 0; p < 4; p++) {
            ulonglong2 hv = hp[p];
            acc0[2*p]   = fma2(hv.x, w2a, acc0[2*p]);
            acc0[2*p+1] = fma2(hv.y, w2a, acc0[2*p+1]);
            acc1[2*p]   = fma2(hv.x, w2b, acc1[2*p]);
            acc1[2*p+1] = fma2(hv.y, w2b, acc1[2*p+1]);
        }
    }

    if (ca_ok) {
        float bo = bout[ca_c];
#pragma unroll
        for (int p = 0; p < 8; p++) {
            float f0, f1;
            asm("mov.b64 {%0, %1}, %2;" : "=f"(f0), "=f"(f1) : "l"(acc0[p]));
            int b0r = bq*16 + 2*p;
            out[(size_t)b0r*V + ca]     = f0 + bo;
            out[(size_t)(b0r+1)*V + ca] = f1 + bo;
        }
    }
    if (cb_ok) {
        float bo = bout[cb_c];
#pragma unroll
        for (int p = 0; p < 8; p++) {
            float f0, f1;
            asm("mov.b64 {%0, %1}, %2;" : "=f"(f0), "=f"(f1) : "l"(acc1[p]));
            int b0r = bq*16 + 2*p;
            out[(size_t)b0r*V + cb]     = f0 + bo;
            out[(size_t)(b0r+1)*V + cb] = f1 + bo;
        }
    }
}

// ==========================================================================
extern "C" void kernel_launch(void* const* d_in, const int* in_sizes, int n_in,
                              void* d_out, int out_size)
{
    const int*   token_id = (const int*)  d_in[0];
    const float* c0       = (const float*)d_in[1];
    const float* h0       = (const float*)d_in[2];
    const float* attn_mem = (const float*)d_in[3];
    const int*   step_p   = (const int*)  d_in[4];
    const float* emb      = (const float*)d_in[5];
    const float* Wi       = (const float*)d_in[6];
    const float* Uh       = (const float*)d_in[7];
    const float* bL       = (const float*)d_in[8];
    const float* Wq       = (const float*)d_in[9];
    const float* bq       = (const float*)d_in[10];
    const float* Wk       = (const float*)d_in[11];
    const float* bk       = (const float*)d_in[12];
    const float* Wv       = (const float*)d_in[13];
    const float* bv       = (const float*)d_in[14];
    const float* Wmix     = (const float*)d_in[15];
    const float* bmix     = (const float*)d_in[16];
    const float* lns      = (const float*)d_in[17];
    const float* lnb      = (const float*)d_in[18];
    const float* Wout     = (const float*)d_in[19];
    const float* bout     = (const float*)d_in[20];
    float* out = (float*)d_out;

    k_lstm<<<32, 256>>>(token_id, c0, h0, emb, Wi, Uh, bL, Wq, bq, Wk, bk, out);
    dim3 g2(CHUNKS, B);
    k_attn_copy<<<g2, 256>>>(attn_mem, step_p, out);
    k_reduce_mix<<<B, 256>>>(step_p, Wv, bv, Wmix, bmix, lns, lnb);
    dim3 g4((V + 511)/512, 4);
    k_logits<<<g4, 256>>>(Wout, bout, out);
}